// round 9
// baseline (speedup 1.0000x reference)
#include <cuda_runtime.h>

// HMM forward, fp32, FFMA2 (packed f32x2), j-pair packing + dup-alpha.
// Shapes: UNITS=256, N=64, S=4, BATCH=64, T=1024.
// Grid: 256 blocks (1 unit each) x 256 threads; tile = 2 batches x 8 states.
// alpha: DUPLICATED ({w,w} per f2), double-buffered, row stride 528B with a
// (row>>3)*16B swizzle shift -> all v2.b64 accesses 16B-aligned, stores at the
// 4-phase floor, loads broadcast. A: half-split chunk permutation -> both
// mainloop A loads bank-conflict-free.

#define NU 256
#define NN 64
#define NS 4
#define NB 64
#define NT 1024
#define RWB 528                      // alpha row stride bytes (66 f2)
#define ABUF_BYTES 33920             // 63*528 + 7*16 + 512, rounded to 128

typedef unsigned long long f2;

__device__ __forceinline__ f2 pack2(float a, float b) {
    f2 r; asm("mov.b64 %0, {%1, %2};" : "=l"(r) : "f"(a), "f"(b)); return r;
}
__device__ __forceinline__ void unpack2(f2 v, float& a, float& b) {
    asm("mov.b64 {%0, %1}, %2;" : "=f"(a), "=f"(b) : "l"(v));
}
__device__ __forceinline__ f2 fma2(f2 a, f2 b, f2 c) {
    f2 d; asm("fma.rn.f32x2 %0, %1, %2, %3;" : "=l"(d) : "l"(a), "l"(b), "l"(c)); return d;
}
__device__ __forceinline__ f2 mul2(f2 a, f2 b) {
    f2 d; asm("mul.rn.f32x2 %0, %1, %2;" : "=l"(d) : "l"(a), "l"(b)); return d;
}
__device__ __forceinline__ f2 add2(f2 a, f2 b) {
    f2 d; asm("add.rn.f32x2 %0, %1, %2;" : "=l"(d) : "l"(a), "l"(b)); return d;
}

// smem map (bytes from base):
//   [0, 67840)          alpha, 2 buffers of ABUF_BYTES
//   [67840, 84224)      A (swizzled), 16384
//   [84224, 86272)      x double buffer, 2*64*16
//   [86272, 87296)      B_sh
//   [87296, 87552)      I_sh
//   [87552, 87556)      Isum
#define OFF_A    67840
#define OFF_X    84224
#define OFF_B    86272
#define OFF_I    87296
#define OFF_ISUM 87552
#define SMEM_TOTAL 87616

__global__ void __launch_bounds__(256, 2) hmm_fwd_kernel(
    const float* __restrict__ x,      // [B, T, S]
    const float* __restrict__ trans,  // [U, N, N]
    const float* __restrict__ emis,   // [U, N, S]
    const float* __restrict__ initk,  // [U, N]
    float* __restrict__ out)          // [B, T, U]
{
    extern __shared__ char smem_raw[];
    float* A_sh = (float*)(smem_raw + OFF_A);
    float4 (*x_sh)[NB] = (float4 (*)[NB])(smem_raw + OFF_X);
    float* B_sh = (float*)(smem_raw + OFF_B);
    float* I_sh = (float*)(smem_raw + OFF_I);
    float* Isum = (float*)(smem_raw + OFF_ISUM);

    const int tid  = threadIdx.x;
    const int u    = blockIdx.x;
    const int jgrp = tid & 7;          // 8 j-groups of 8 states
    const int bgrp = tid >> 3;         // 32 b-groups of 2 batches
    const int j0   = jgrp * 8;
    const int b0   = bgrp * 2;

    // ---------------- setup ----------------
    const float* Tu = trans + u * NN * NN;
    for (int idx = tid; idx < NN * NN; idx += 256) A_sh[idx] = Tu[idx];

    if (tid < NN) {
        const float* Eu = emis + (u * NN + tid) * NS;
        float e0 = expf(Eu[0]), e1 = expf(Eu[1]), e2 = expf(Eu[2]), e3 = expf(Eu[3]);
        float r = 1.0f / ((e0 + e1) + (e2 + e3));
        B_sh[tid * 4 + 0] = e0 * r; B_sh[tid * 4 + 1] = e1 * r;
        B_sh[tid * 4 + 2] = e2 * r; B_sh[tid * 4 + 3] = e3 * r;
        I_sh[tid] = expf(initk[u * NN + tid]);
        x_sh[0][tid] = ((const float4*)x)[(size_t)tid * NT + 0];  // x_0
        x_sh[1][tid] = ((const float4*)x)[(size_t)tid * NT + 1];  // x_1
    }
    __syncthreads();

    if (tid < NN) {  // row softmax of transition row tid (linear layout)
        float s = 0.0f;
        #pragma unroll 8
        for (int j = 0; j < NN; ++j) {
            float e = expf(A_sh[tid * NN + j]);
            A_sh[tid * NN + j] = e;
            s += e;
        }
        float r = 1.0f / s;
        #pragma unroll 8
        for (int j = 0; j < NN; ++j) A_sh[tid * NN + j] *= r;
    }
    if (tid == 0) {
        float s = 0.0f;
        #pragma unroll 8
        for (int k = 0; k < NN; ++k) s += I_sh[k];
        *Isum = 1.0f / s;
    }
    __syncthreads();

    // ---- A swizzle pass: 16B chunk c of each row -> position ((c&1)<<3)|(c>>1)
    // (row chunk for states [8g..8g+3] at g*16B, [8g+4..8g+7] at 128+g*16B)
    {
        float tmp[16];
        #pragma unroll
        for (int k2 = 0; k2 < 16; ++k2) tmp[k2] = A_sh[tid * 16 + k2];
        __syncthreads();
        #pragma unroll
        for (int k2 = 0; k2 < 16; ++k2) {
            int idx = tid * 16 + k2;
            int i = idx >> 6, j = idx & 63;
            int c = j >> 2, k = j & 3;
            int p = ((c & 1) << 3) | (c >> 1);
            A_sh[i * 64 + p * 4 + k] = tmp[k2];
        }
        __syncthreads();
    }

    // per-thread constants (j-pair packed)
    const float inv = *Isum;
    f2 Breg2[4][4];   // [j-pair][channel]
    f2 Ireg2[4];
    #pragma unroll
    for (int jp = 0; jp < 4; ++jp) {
        int ja = j0 + 2 * jp, jb = ja + 1;
        #pragma unroll
        for (int c = 0; c < 4; ++c)
            Breg2[jp][c] = pack2(B_sh[ja * 4 + c], B_sh[jb * 4 + c]);
        Ireg2[jp] = pack2(I_sh[ja] * inv, I_sh[jb] * inv);
    }
    float ll[2] = {0.0f, 0.0f};

    const unsigned alBase = (unsigned)__cvta_generic_to_shared(smem_raw);
    const unsigned aBase  = (unsigned)__cvta_generic_to_shared(A_sh) + (unsigned)(jgrp * 16);
    // this thread's store rows: rE = j0 + 2jp  ->  offset rE*528 + jgrp*16
    const unsigned myRowShift = (unsigned)(j0 * RWB + jgrp * 16);

    // ---------------- shared epilogue ----------------
    auto epilogue = [&](f2 (&acc)[2][4], int t) {
        const unsigned wrBase = alBase + ((t + 1) & 1) * ABUF_BYTES
                                + myRowShift + (unsigned)(bgrp * 16);
        f2 fw2[2][4];
        float s[2];
        #pragma unroll
        for (int b = 0; b < 2; ++b) {
            float4 xv = x_sh[t & 1][b0 + b];
            f2 xc0 = pack2(xv.x, xv.x), xc1 = pack2(xv.y, xv.y);
            f2 xc2 = pack2(xv.z, xv.z), xc3 = pack2(xv.w, xv.w);
            #pragma unroll
            for (int jp = 0; jp < 4; ++jp) {
                f2 e = mul2(Breg2[jp][0], xc0);
                e = fma2(Breg2[jp][1], xc1, e);
                e = fma2(Breg2[jp][2], xc2, e);
                e = fma2(Breg2[jp][3], xc3, e);
                fw2[b][jp] = mul2(e, acc[b][jp]);
            }
            f2 t01 = add2(fw2[b][0], fw2[b][1]);
            f2 t23 = add2(fw2[b][2], fw2[b][3]);
            f2 ts  = add2(t01, t23);
            float sa, sb; unpack2(ts, sa, sb);
            s[b] = sa + sb;
        }
        // reduce over the 8 j-groups (lane bits 0..2); bit-exact per lane
        #pragma unroll
        for (int m = 1; m < 8; m <<= 1) {
            s[0] += __shfl_xor_sync(0xffffffffu, s[0], m);
            s[1] += __shfl_xor_sync(0xffffffffu, s[1], m);
        }
        if (jgrp == 0) {
            #pragma unroll
            for (int b = 0; b < 2; ++b) {
                ll[b] += __logf(s[b]);
                out[((size_t)(b0 + b) * NT + t) * NU + u] = ll[b];
            }
        }
        #pragma unroll
        for (int b = 0; b < 2; ++b) {
            float r = __fdividef(1.0f, s[b]);
            f2 r2 = pack2(r, r);
            #pragma unroll
            for (int jp = 0; jp < 4; ++jp) fw2[b][jp] = mul2(fw2[b][jp], r2);
        }
        // write alpha duplicated: row j gets {w,w} per batch
        #pragma unroll
        for (int jp = 0; jp < 4; ++jp) {
            float a0, a1, c0, c1;
            unpack2(fw2[0][jp], a0, a1);   // batch b0 : states (even, odd)
            unpack2(fw2[1][jp], c0, c1);   // batch b0+1
            unsigned rowE = wrBase + (unsigned)(2 * jp * RWB);
            unsigned rowO = rowE + RWB;
            f2 p0 = pack2(a0, a0), p1 = pack2(c0, c0);
            f2 q0 = pack2(a1, a1), q1 = pack2(c1, c1);
            asm volatile("st.shared.v2.b64 [%0], {%1, %2};" :: "r"(rowE), "l"(p0), "l"(p1));
            asm volatile("st.shared.v2.b64 [%0], {%1, %2};" :: "r"(rowO), "l"(q0), "l"(q1));
        }
    };

    // ---------------- t = 0 (init-distribution path) ----------------
    {
        f2 acc0[2][4];
        #pragma unroll
        for (int b = 0; b < 2; ++b)
            #pragma unroll
            for (int jp = 0; jp < 4; ++jp) acc0[b][jp] = Ireg2[jp];
        epilogue(acc0, 0);   // writes buffer 1, outputs t=0
        __syncthreads();
    }

    // ---------------- time loop ----------------
    for (int t = 1; t < NT; ++t) {
        if (tid < NB && (t + 1) < NT)
            x_sh[(t + 1) & 1][tid] = ((const float4*)x)[(size_t)tid * NT + (t + 1)];

        f2 acc[2][4];
        #pragma unroll
        for (int b = 0; b < 2; ++b)
            #pragma unroll
            for (int jp = 0; jp < 4; ++jp) acc[b][jp] = 0ull;

        unsigned aPtr  = aBase;
        // alpha read base for this buffer; row i at i*528 + (i>>3)*16
        unsigned alPtr = alBase + (t & 1) * ABUF_BYTES + (unsigned)(bgrp * 16);

        #pragma unroll
        for (int ib = 0; ib < 8; ++ib) {
            #pragma unroll
            for (int ii = 0; ii < 8; ++ii) {
                f2 a01, a23, a45, a67, d0, d1;
                unsigned ap = aPtr + (unsigned)(ii * 256);
                unsigned dp = alPtr + (unsigned)(ii * RWB);
                asm("ld.shared.v2.b64 {%0, %1}, [%2];" : "=l"(a01), "=l"(a23) : "r"(ap));
                asm("ld.shared.v2.b64 {%0, %1}, [%2];" : "=l"(a45), "=l"(a67) : "r"(ap + 128));
                asm("ld.shared.v2.b64 {%0, %1}, [%2];" : "=l"(d0),  "=l"(d1)  : "r"(dp));
                acc[0][0] = fma2(d0, a01, acc[0][0]);
                acc[0][1] = fma2(d0, a23, acc[0][1]);
                acc[0][2] = fma2(d0, a45, acc[0][2]);
                acc[0][3] = fma2(d0, a67, acc[0][3]);
                acc[1][0] = fma2(d1, a01, acc[1][0]);
                acc[1][1] = fma2(d1, a23, acc[1][1]);
                acc[1][2] = fma2(d1, a45, acc[1][2]);
                acc[1][3] = fma2(d1, a67, acc[1][3]);
            }
            aPtr  += 8 * 256;            // 2048
            alPtr += 8 * RWB + 16;       // 4240 (swizzle shift every 8 rows)
        }

        epilogue(acc, t);
        __syncthreads();
    }
}

extern "C" void kernel_launch(void* const* d_in, const int* in_sizes, int n_in,
                              void* d_out, int out_size) {
    const float* x     = (const float*)d_in[0];  // [64,1024,4]
    const float* trans = (const float*)d_in[1];  // [256,64,64]
    const float* emis  = (const float*)d_in[2];  // [256,64,4]
    const float* initk = (const float*)d_in[3];  // [256,64]
    float* out = (float*)d_out;                  // [64,1024,256]
    (void)in_sizes; (void)n_in; (void)out_size;

    cudaFuncSetAttribute(hmm_fwd_kernel,
                         cudaFuncAttributeMaxDynamicSharedMemorySize, SMEM_TOTAL);
    hmm_fwd_kernel<<<NU, 256, SMEM_TOTAL>>>(x, trans, emis, initk, out);
}

// round 10
// speedup vs baseline: 4.0611x; 4.0611x over previous
#include <cuda_runtime.h>

// HMM forward, fp32, FFMA2 (packed f32x2), j-pair packing + dup-alpha.
// Shapes: UNITS=256, N=64, S=4, BATCH=64, T=1024.
// Grid: 256 blocks (1 unit) x 256 threads; tile = 2 batches x 8 states.
// alpha: DUPLICATED ({w,w} per f2), double-buffered, row stride 528B with
// (row>>3)*16B swizzle -> 16B-aligned v2.b64, 4-phase stores, broadcast loads.
// A: half-split chunk permutation -> mainloop A loads conflict-free.
// R9: register diet — B/I constants live in smem (not regs), no lambda,
// t=0 handled by uniform branch. Target <= ~104 regs, zero spills.

#define NU 256
#define NN 64
#define NS 4
#define NB 64
#define NT 1024
#define RWB 528                      // alpha row stride bytes (66 f2)
#define ABUF_BYTES 33920

typedef unsigned long long f2;

__device__ __forceinline__ f2 pack2(float a, float b) {
    f2 r; asm("mov.b64 %0, {%1, %2};" : "=l"(r) : "f"(a), "f"(b)); return r;
}
__device__ __forceinline__ void unpack2(f2 v, float& a, float& b) {
    asm("mov.b64 {%0, %1}, %2;" : "=f"(a), "=f"(b) : "l"(v));
}
__device__ __forceinline__ f2 fma2(f2 a, f2 b, f2 c) {
    f2 d; asm("fma.rn.f32x2 %0, %1, %2, %3;" : "=l"(d) : "l"(a), "l"(b), "l"(c)); return d;
}
__device__ __forceinline__ f2 mul2(f2 a, f2 b) {
    f2 d; asm("mul.rn.f32x2 %0, %1, %2;" : "=l"(d) : "l"(a), "l"(b)); return d;
}
__device__ __forceinline__ f2 add2(f2 a, f2 b) {
    f2 d; asm("add.rn.f32x2 %0, %1, %2;" : "=l"(d) : "l"(a), "l"(b)); return d;
}
__device__ __forceinline__ f2 lds8(unsigned a) {
    f2 v; asm("ld.shared.b64 %0, [%1];" : "=l"(v) : "r"(a)); return v;
}

// smem map (bytes from base):
//   [0, 67840)       alpha, 2 buffers
//   [67840, 84224)   A (swizzled), 16384
//   [84224, 86272)   x double buffer, 2*64*16
//   [86272, 87296)   B2: f2[4][32]  (1024 B)
//   [87296, 87552)   I_sh (64 f)
//   [87552, 87556)   Isum
#define OFF_A    67840
#define OFF_X    84224
#define OFF_B2   86272
#define OFF_I    87296
#define OFF_ISUM 87552
#define SMEM_TOTAL 87616

__global__ void __launch_bounds__(256, 2) hmm_fwd_kernel(
    const float* __restrict__ x,      // [B, T, S]
    const float* __restrict__ trans,  // [U, N, N]
    const float* __restrict__ emis,   // [U, N, S]
    const float* __restrict__ initk,  // [U, N]
    float* __restrict__ out)          // [B, T, U]
{
    extern __shared__ char smem_raw[];
    float* A_sh = (float*)(smem_raw + OFF_A);
    float4 (*x_sh)[NB] = (float4 (*)[NB])(smem_raw + OFF_X);
    f2*    B2_sh = (f2*)(smem_raw + OFF_B2);   // [4][32] : [channel][jpair]
    float* I_sh  = (float*)(smem_raw + OFF_I);
    float* Isum  = (float*)(smem_raw + OFF_ISUM);

    const int tid  = threadIdx.x;
    const int u    = blockIdx.x;
    const int jgrp = tid & 7;          // 8 j-groups of 8 states
    const int bgrp = tid >> 3;         // 32 b-groups of 2 batches
    const int j0   = jgrp * 8;
    const int b0   = bgrp * 2;

    // ---------------- setup ----------------
    const float* Tu = trans + u * NN * NN;
    for (int idx = tid; idx < NN * NN; idx += 256) A_sh[idx] = Tu[idx];

    if (tid < 32) {
        // emission softmax for rows 2*tid, 2*tid+1, packed as dup f2
        const float* Ea = emis + (u * NN + 2 * tid) * NS;
        const float* Eb = Ea + NS;
        float a0 = expf(Ea[0]), a1 = expf(Ea[1]), a2 = expf(Ea[2]), a3 = expf(Ea[3]);
        float b0_ = expf(Eb[0]), b1 = expf(Eb[1]), b2 = expf(Eb[2]), b3 = expf(Eb[3]);
        float ra = 1.0f / ((a0 + a1) + (a2 + a3));
        float rb = 1.0f / ((b0_ + b1) + (b2 + b3));
        B2_sh[0 * 32 + tid] = pack2(a0 * ra, b0_ * rb);
        B2_sh[1 * 32 + tid] = pack2(a1 * ra, b1 * rb);
        B2_sh[2 * 32 + tid] = pack2(a2 * ra, b2 * rb);
        B2_sh[3 * 32 + tid] = pack2(a3 * ra, b3 * rb);
    }
    if (tid < NN) {
        I_sh[tid] = expf(initk[u * NN + tid]);
        x_sh[0][tid] = ((const float4*)x)[(size_t)tid * NT + 0];  // x_0
    }
    __syncthreads();

    if (tid < NN) {  // row softmax of transition row tid (linear layout)
        float s = 0.0f;
        #pragma unroll 8
        for (int j = 0; j < NN; ++j) {
            float e = expf(A_sh[tid * NN + j]);
            A_sh[tid * NN + j] = e;
            s += e;
        }
        float r = 1.0f / s;
        #pragma unroll 8
        for (int j = 0; j < NN; ++j) A_sh[tid * NN + j] *= r;
    }
    if (tid == 0) {
        float s = 0.0f;
        #pragma unroll 8
        for (int k = 0; k < NN; ++k) s += I_sh[k];
        *Isum = 1.0f / s;
    }
    __syncthreads();

    // ---- A swizzle: 16B chunk c of each row -> position ((c&1)<<3)|(c>>1)
    {
        float tmp[16];
        #pragma unroll
        for (int k2 = 0; k2 < 16; ++k2) tmp[k2] = A_sh[tid * 16 + k2];
        __syncthreads();
        #pragma unroll
        for (int k2 = 0; k2 < 16; ++k2) {
            int idx = tid * 16 + k2;
            int i = idx >> 6, j = idx & 63;
            int c = j >> 2, k = j & 3;
            int p = ((c & 1) << 3) | (c >> 1);
            A_sh[i * 64 + p * 4 + k] = tmp[k2];
        }
    }
    if (tid < NN) I_sh[tid] *= *Isum;   // normalize init in place
    __syncthreads();

    float ll0 = 0.0f, ll1 = 0.0f;

    const unsigned smBase = (unsigned)__cvta_generic_to_shared(smem_raw);
    const unsigned aBase  = smBase + OFF_A + (unsigned)(jgrp * 16);
    const unsigned b2Base = smBase + OFF_B2 + (unsigned)((bgrp & 0) + ( (j0 >> 1) * 8));
    const unsigned iBase  = smBase + OFF_I + (unsigned)(j0 * 4);

    // ---------------- time loop ----------------
    for (int t = 0; t < NT; ++t) {
        if (tid < NB && (t + 1) < NT)
            x_sh[(t + 1) & 1][tid] = ((const float4*)x)[(size_t)tid * NT + (t + 1)];

        f2 acc[2][4];
        if (t == 0) {
            // R = I (alpha = 0, init path); dup-load I pairs from smem
            #pragma unroll
            for (int jp = 0; jp < 4; ++jp) {
                float ia, ib;
                asm("ld.shared.v2.f32 {%0, %1}, [%2];"
                    : "=f"(ia), "=f"(ib) : "r"(iBase + (unsigned)(jp * 8)));
                acc[0][jp] = pack2(ia, ib);
                acc[1][jp] = acc[0][jp];
            }
        } else {
            #pragma unroll
            for (int b = 0; b < 2; ++b)
                #pragma unroll
                for (int jp = 0; jp < 4; ++jp) acc[b][jp] = 0ull;

            unsigned aPtr  = aBase;
            unsigned alPtr = smBase + (t & 1) * ABUF_BYTES + (unsigned)(bgrp * 16);
            #pragma unroll
            for (int ib = 0; ib < 8; ++ib) {
                #pragma unroll
                for (int ii = 0; ii < 8; ++ii) {
                    f2 a01, a23, a45, a67, d0, d1;
                    unsigned ap = aPtr + (unsigned)(ii * 256);
                    unsigned dp = alPtr + (unsigned)(ii * RWB);
                    asm("ld.shared.v2.b64 {%0, %1}, [%2];" : "=l"(a01), "=l"(a23) : "r"(ap));
                    asm("ld.shared.v2.b64 {%0, %1}, [%2];" : "=l"(a45), "=l"(a67) : "r"(ap + 128));
                    asm("ld.shared.v2.b64 {%0, %1}, [%2];" : "=l"(d0),  "=l"(d1)  : "r"(dp));
                    acc[0][0] = fma2(d0, a01, acc[0][0]);
                    acc[0][1] = fma2(d0, a23, acc[0][1]);
                    acc[0][2] = fma2(d0, a45, acc[0][2]);
                    acc[0][3] = fma2(d0, a67, acc[0][3]);
                    acc[1][0] = fma2(d1, a01, acc[1][0]);
                    acc[1][1] = fma2(d1, a23, acc[1][1]);
                    acc[1][2] = fma2(d1, a45, acc[1][2]);
                    acc[1][3] = fma2(d1, a67, acc[1][3]);
                }
                aPtr  += 8 * 256;
                alPtr += 8 * RWB + 16;   // swizzle shift every 8 rows
            }
        }

        // ---------------- epilogue (inline) ----------------
        f2 fw2[2][4];
        float s0, s1;
        #pragma unroll
        for (int b = 0; b < 2; ++b) {
            float4 xv = x_sh[t & 1][b0 + b];
            f2 xc0 = pack2(xv.x, xv.x), xc1 = pack2(xv.y, xv.y);
            f2 xc2 = pack2(xv.z, xv.z), xc3 = pack2(xv.w, xv.w);
            #pragma unroll
            for (int jp = 0; jp < 4; ++jp) {
                unsigned bp = b2Base + (unsigned)(jp * 8);
                f2 e = mul2(lds8(bp), xc0);
                e = fma2(lds8(bp + 256), xc1, e);
                e = fma2(lds8(bp + 512), xc2, e);
                e = fma2(lds8(bp + 768), xc3, e);
                fw2[b][jp] = mul2(e, acc[b][jp]);
            }
            f2 ts = add2(add2(fw2[b][0], fw2[b][1]), add2(fw2[b][2], fw2[b][3]));
            float sa, sb; unpack2(ts, sa, sb);
            if (b == 0) s0 = sa + sb; else s1 = sa + sb;
        }
        // reduce over the 8 j-groups (lane bits 0..2); bit-exact per lane
        #pragma unroll
        for (int m = 1; m < 8; m <<= 1) {
            s0 += __shfl_xor_sync(0xffffffffu, s0, m);
            s1 += __shfl_xor_sync(0xffffffffu, s1, m);
        }
        if (jgrp == 0) {
            ll0 += __logf(s0);
            ll1 += __logf(s1);
            out[((size_t)(b0 + 0) * NT + t) * NU + u] = ll0;
            out[((size_t)(b0 + 1) * NT + t) * NU + u] = ll1;
        }

        {
            float r0 = __fdividef(1.0f, s0);
            float r1 = __fdividef(1.0f, s1);
            f2 rr0 = pack2(r0, r0), rr1 = pack2(r1, r1);
            const unsigned wrBase = smBase + ((t + 1) & 1) * ABUF_BYTES
                + (unsigned)(j0 * RWB + jgrp * 16 + bgrp * 16);
            #pragma unroll
            for (int jp = 0; jp < 4; ++jp) {
                f2 v0 = mul2(fw2[0][jp], rr0);   // batch b0: states (even, odd)
                f2 v1 = mul2(fw2[1][jp], rr1);   // batch b0+1
                float a0, a1, c0, c1;
                unpack2(v0, a0, a1);
                unpack2(v1, c0, c1);
                unsigned rowE = wrBase + (unsigned)(2 * jp * RWB);
                f2 p0 = pack2(a0, a0), p1 = pack2(c0, c0);
                f2 q0 = pack2(a1, a1), q1 = pack2(c1, c1);
                asm volatile("st.shared.v2.b64 [%0], {%1, %2};" :: "r"(rowE), "l"(p0), "l"(p1));
                asm volatile("st.shared.v2.b64 [%0], {%1, %2};" :: "r"(rowE + RWB), "l"(q0), "l"(q1));
            }
        }
        __syncthreads();
    }
}

extern "C" void kernel_launch(void* const* d_in, const int* in_sizes, int n_in,
                              void* d_out, int out_size) {
    const float* x     = (const float*)d_in[0];  // [64,1024,4]
    const float* trans = (const float*)d_in[1];  // [256,64,64]
    const float* emis  = (const float*)d_in[2];  // [256,64,4]
    const float* initk = (const float*)d_in[3];  // [256,64]
    float* out = (float*)d_out;                  // [64,1024,256]
    (void)in_sizes; (void)n_in; (void)out_size;

    cudaFuncSetAttribute(hmm_fwd_kernel,
                         cudaFuncAttributeMaxDynamicSharedMemorySize, SMEM_TOTAL);
    hmm_fwd_kernel<<<NU, 256, SMEM_TOTAL>>>(x, trans, emis, initk, out);
}

// round 13
// speedup vs baseline: 7.2376x; 1.7822x over previous
#include <cuda_runtime.h>

// HMM forward, fp32 accum, FFMA2 (packed f32x2). R11: crossbar diet.
// Shapes: UNITS=256, N=64, S=4, BATCH=64, T=1024.
// Grid: 256 blocks (1 unit) x 128 threads; tile = 4 batches x 8 states.
// A: bf16 j-pairs in smem (16 B/lane/i), expanded to f32x2 via shift/and (ALU).
// alpha: f32 un-duplicated, double-buffered, row stride 256B + (row>>3)*16B
// swizzle -> conflict-free stores, broadcast loads. 8 phases/warp/i total.

#define NU 256
#define NN 64
#define NS 4
#define NB 64
#define NT 1024
#define ARS 256                  // alpha row stride bytes (64 f32)
#define ABUF 16512               // 64*256 + 7*16, padded
#define OFF_ABF 33024            // A bf16: 64 rows * 128 B = 8192
#define OFF_X   41216            // x double buffer: 2*64*16 = 2048
#define OFF_B2  43264            // B2: f2[4][32] = 1024
#define OFF_I   44288            // I: 64 f32
#define OFF_ISUM 44544
#define SMEM_TOTAL 44672

typedef unsigned long long f2;

__device__ __forceinline__ f2 pack2(float a, float b) {
    f2 r; asm("mov.b64 %0, {%1, %2};" : "=l"(r) : "f"(a), "f"(b)); return r;
}
__device__ __forceinline__ void unpack2(f2 v, float& a, float& b) {
    asm("mov.b64 {%0, %1}, %2;" : "=f"(a), "=f"(b) : "l"(v));
}
__device__ __forceinline__ f2 fma2(f2 a, f2 b, f2 c) {
    f2 d; asm("fma.rn.f32x2 %0, %1, %2, %3;" : "=l"(d) : "l"(a), "l"(b), "l"(c)); return d;
}
__device__ __forceinline__ f2 mul2(f2 a, f2 b) {
    f2 d; asm("mul.rn.f32x2 %0, %1, %2;" : "=l"(d) : "l"(a), "l"(b)); return d;
}
__device__ __forceinline__ f2 add2(f2 a, f2 b) {
    f2 d; asm("add.rn.f32x2 %0, %1, %2;" : "=l"(d) : "l"(a), "l"(b)); return d;
}
__device__ __forceinline__ f2 lds8(unsigned a) {
    f2 v; asm("ld.shared.b64 %0, [%1];" : "=l"(v) : "r"(a)); return v;
}
// bf16x2 word {hi: bf(odd state), lo: bf(even state)} -> f32x2 {f(even), f(odd)}
__device__ __forceinline__ f2 bfexp(unsigned w) {
    f2 r;
    asm("{\n\t.reg .b32 lo, hi;\n\t"
        "shl.b32 lo, %1, 16;\n\t"
        "and.b32 hi, %1, 0xffff0000;\n\t"
        "mov.b64 %0, {lo, hi};\n\t}"
        : "=l"(r) : "r"(w));
    return r;
}

__global__ void __launch_bounds__(128, 2) hmm_fwd_kernel(
    const float* __restrict__ x,      // [B, T, S]
    const float* __restrict__ trans,  // [U, N, N]
    const float* __restrict__ emis,   // [U, N, S]
    const float* __restrict__ initk,  // [U, N]
    float* __restrict__ out)          // [B, T, U]
{
    extern __shared__ char sm[];
    float*    Astage = (float*)sm;                       // staging in alpha buf 0
    unsigned* Abf    = (unsigned*)(sm + OFF_ABF);        // bf16x2 words [64][32]
    float4 (*x_sh)[NB] = (float4 (*)[NB])(sm + OFF_X);
    f2*    B2_sh = (f2*)(sm + OFF_B2);                   // [4 ch][32 jpairs]
    float* I_sh  = (float*)(sm + OFF_I);
    float* Isum  = (float*)(sm + OFF_ISUM);

    const int tid  = threadIdx.x;
    const int u    = blockIdx.x;
    const int jgrp = tid & 7;          // 8 j-groups of 8 states
    const int bgrp = tid >> 3;         // 16 b-groups of 4 batches
    const int j0   = jgrp * 8;
    const int b0   = bgrp * 4;

    // ---------------- setup ----------------
    const float* Tu = trans + u * NN * NN;
    for (int idx = tid; idx < NN * NN; idx += 128) Astage[idx] = Tu[idx];

    if (tid < 32) {   // emission softmax, dup-packed f2 per j-pair
        const float* Ea = emis + (u * NN + 2 * tid) * NS;
        const float* Eb = Ea + NS;
        float a0 = expf(Ea[0]), a1 = expf(Ea[1]), a2 = expf(Ea[2]), a3 = expf(Ea[3]);
        float c0 = expf(Eb[0]), c1 = expf(Eb[1]), c2 = expf(Eb[2]), c3 = expf(Eb[3]);
        float ra = 1.0f / ((a0 + a1) + (a2 + a3));
        float rb = 1.0f / ((c0 + c1) + (c2 + c3));
        B2_sh[0 * 32 + tid] = pack2(a0 * ra, c0 * rb);
        B2_sh[1 * 32 + tid] = pack2(a1 * ra, c1 * rb);
        B2_sh[2 * 32 + tid] = pack2(a2 * ra, c2 * rb);
        B2_sh[3 * 32 + tid] = pack2(a3 * ra, c3 * rb);
    }
    if (tid < NN) {
        I_sh[tid] = expf(initk[u * NN + tid]);
        x_sh[0][tid] = ((const float4*)x)[(size_t)tid * NT + 0];
    }
    __syncthreads();

    if (tid < NN) {   // transition row softmax in f32 staging
        float s = 0.0f;
        #pragma unroll 8
        for (int j = 0; j < NN; ++j) {
            float e = expf(Astage[tid * NN + j]);
            Astage[tid * NN + j] = e;
            s += e;
        }
        float r = 1.0f / s;
        #pragma unroll 8
        for (int j = 0; j < NN; ++j) Astage[tid * NN + j] *= r;
    }
    if (tid == 0) {
        float s = 0.0f;
        #pragma unroll 8
        for (int k = 0; k < NN; ++k) s += I_sh[k];
        *Isum = 1.0f / s;
    }
    __syncthreads();

    // pack A -> bf16x2 words: word (i, rem) holds states (8*(rem>>2) + 2*(rem&3)) +0/+1
    for (int idx = tid; idx < NN * 32; idx += 128) {
        int i = idx >> 5, rem = idx & 31;
        int s0 = (rem >> 2) * 8 + (rem & 3) * 2;
        float fe = Astage[i * NN + s0], fo = Astage[i * NN + s0 + 1];
        unsigned w;
        asm("cvt.rn.bf16x2.f32 %0, %1, %2;" : "=r"(w) : "f"(fo), "f"(fe));
        Abf[i * 32 + rem] = w;
    }
    if (tid < NN) I_sh[tid] *= *Isum;
    __syncthreads();

    float ll[4] = {0.0f, 0.0f, 0.0f, 0.0f};

    const unsigned smBase = (unsigned)__cvta_generic_to_shared(sm);
    const unsigned aBase  = smBase + OFF_ABF + (unsigned)(jgrp * 16);
    const unsigned b2Base = smBase + OFF_B2 + (unsigned)((j0 >> 1) * 8);
    const unsigned iBase  = smBase + OFF_I + (unsigned)(j0 * 4);

    // ---------------- time loop ----------------
    for (int t = 0; t < NT; ++t) {
        if (tid < NB && (t + 1) < NT)
            x_sh[(t + 1) & 1][tid] = ((const float4*)x)[(size_t)tid * NT + (t + 1)];

        f2 acc[4][4];   // [batch][j-pair]
        if (t == 0) {
            #pragma unroll
            for (int jp = 0; jp < 4; ++jp) {
                float ia, ib;
                asm("ld.shared.v2.f32 {%0, %1}, [%2];"
                    : "=f"(ia), "=f"(ib) : "r"(iBase + (unsigned)(jp * 8)));
                f2 v = pack2(ia, ib);
                acc[0][jp] = v; acc[1][jp] = v; acc[2][jp] = v; acc[3][jp] = v;
            }
        } else {
            #pragma unroll
            for (int b = 0; b < 4; ++b)
                #pragma unroll
                for (int jp = 0; jp < 4; ++jp) acc[b][jp] = 0ull;

            unsigned aPtr = aBase;
            unsigned dPtr = smBase + (t & 1) * ABUF + (unsigned)(bgrp * 16);
            for (int ib = 0; ib < 8; ++ib) {
                #pragma unroll
                for (int ii = 0; ii < 8; ++ii) {
                    unsigned w0, w1, w2, w3;
                    float d0, d1, d2, d3;
                    asm("ld.shared.v4.b32 {%0,%1,%2,%3}, [%4];"
                        : "=r"(w0), "=r"(w1), "=r"(w2), "=r"(w3)
                        : "r"(aPtr + (unsigned)(ii * 128)));
                    asm("ld.shared.v4.f32 {%0,%1,%2,%3}, [%4];"
                        : "=f"(d0), "=f"(d1), "=f"(d2), "=f"(d3)
                        : "r"(dPtr + (unsigned)(ii * ARS)));
                    f2 A0 = bfexp(w0), A1 = bfexp(w1), A2 = bfexp(w2), A3 = bfexp(w3);
                    f2 l0 = pack2(d0, d0), l1 = pack2(d1, d1);
                    f2 l2 = pack2(d2, d2), l3 = pack2(d3, d3);
                    acc[0][0] = fma2(l0, A0, acc[0][0]);
                    acc[0][1] = fma2(l0, A1, acc[0][1]);
                    acc[0][2] = fma2(l0, A2, acc[0][2]);
                    acc[0][3] = fma2(l0, A3, acc[0][3]);
                    acc[1][0] = fma2(l1, A0, acc[1][0]);
                    acc[1][1] = fma2(l1, A1, acc[1][1]);
                    acc[1][2] = fma2(l1, A2, acc[1][2]);
                    acc[1][3] = fma2(l1, A3, acc[1][3]);
                    acc[2][0] = fma2(l2, A0, acc[2][0]);
                    acc[2][1] = fma2(l2, A1, acc[2][1]);
                    acc[2][2] = fma2(l2, A2, acc[2][2]);
                    acc[2][3] = fma2(l2, A3, acc[2][3]);
                    acc[3][0] = fma2(l3, A0, acc[3][0]);
                    acc[3][1] = fma2(l3, A1, acc[3][1]);
                    acc[3][2] = fma2(l3, A2, acc[3][2]);
                    acc[3][3] = fma2(l3, A3, acc[3][3]);
                }
                aPtr += 8 * 128;
                dPtr += 8 * ARS + 16;   // swizzle shift every 8 rows
            }
        }

        // ---------------- epilogue ----------------
        f2 Bc[4][4];   // [channel][j-pair], batch-independent
        #pragma unroll
        for (int c = 0; c < 4; ++c)
            #pragma unroll
            for (int jp = 0; jp < 4; ++jp)
                Bc[c][jp] = lds8(b2Base + (unsigned)(c * 256 + jp * 8));

        f2 fw2[4][4];
        float s[4];
        #pragma unroll
        for (int b = 0; b < 4; ++b) {
            float4 xv = x_sh[t & 1][b0 + b];
            f2 x0 = pack2(xv.x, xv.x), x1 = pack2(xv.y, xv.y);
            f2 x2 = pack2(xv.z, xv.z), x3 = pack2(xv.w, xv.w);
            #pragma unroll
            for (int jp = 0; jp < 4; ++jp) {
                f2 e = mul2(Bc[0][jp], x0);
                e = fma2(Bc[1][jp], x1, e);
                e = fma2(Bc[2][jp], x2, e);
                e = fma2(Bc[3][jp], x3, e);
                fw2[b][jp] = mul2(e, acc[b][jp]);
            }
            f2 ts = add2(add2(fw2[b][0], fw2[b][1]), add2(fw2[b][2], fw2[b][3]));
            float sa, sb; unpack2(ts, sa, sb);
            s[b] = sa + sb;
        }
        // reduce over the 8 j-groups (lane bits 0..2); bit-exact per lane
        #pragma unroll
        for (int m = 1; m < 8; m <<= 1)
            #pragma unroll
            for (int b = 0; b < 4; ++b)
                s[b] += __shfl_xor_sync(0xffffffffu, s[b], m);

        if (jgrp == 0) {
            #pragma unroll
            for (int b = 0; b < 4; ++b) {
                ll[b] += __logf(s[b]);
                out[((size_t)(b0 + b) * NT + t) * NU + u] = ll[b];
            }
        }

        {
            const unsigned wrBase = smBase + ((t + 1) & 1) * ABUF
                + (unsigned)(j0 * ARS + jgrp * 16 + bgrp * 16);
            #pragma unroll
            for (int b = 0; b < 4; ++b) {
                float r = __fdividef(1.0f, s[b]);
                f2 r2 = pack2(r, r);
                fw2[b][0] = mul2(fw2[b][0], r2);
                fw2[b][1] = mul2(fw2[b][1], r2);
                fw2[b][2] = mul2(fw2[b][2], r2);
                fw2[b][3] = mul2(fw2[b][3], r2);
            }
            #pragma unroll
            for (int jp = 0; jp < 4; ++jp) {
                float e0, o0, e1, o1, e2, o2, e3, o3;
                unpack2(fw2[0][jp], e0, o0);
                unpack2(fw2[1][jp], e1, o1);
                unpack2(fw2[2][jp], e2, o2);
                unpack2(fw2[3][jp], e3, o3);
                unsigned rowE = wrBase + (unsigned)(2 * jp * ARS);
                asm volatile("st.shared.v4.f32 [%0], {%1,%2,%3,%4};"
                             :: "r"(rowE), "f"(e0), "f"(e1), "f"(e2), "f"(e3));
                asm volatile("st.shared.v4.f32 [%0], {%1,%2,%3,%4};"
                             :: "r"(rowE + ARS), "f"(o0), "f"(o1), "f"(o2), "f"(o3));
            }
        }
        __syncthreads();
    }
}

extern "C" void kernel_launch(void* const* d_in, const int* in_sizes, int n_in,
                              void* d_out, int out_size) {
    const float* x     = (const float*)d_in[0];  // [64,1024,4]
    const float* trans = (const float*)d_in[1];  // [256,64,64]
    const float* emis  = (const float*)d_in[2];  // [256,64,4]
    const float* initk = (const float*)d_in[3];  // [256,64]
    float* out = (float*)d_out;                  // [64,1024,256]
    (void)in_sizes; (void)n_in; (void)out_size;

    cudaFuncSetAttribute(hmm_fwd_kernel,
                         cudaFuncAttributeMaxDynamicSharedMemorySize, SMEM_TOTAL);
    hmm_fwd_kernel<<<NU, 128, SMEM_TOTAL>>>(x, trans, emis, initk, out);
}

// round 14
// speedup vs baseline: 25.0240x; 3.4575x over previous
#include <cuda_runtime.h>

// HMM forward via mma.sync m16n8k16 bf16 (HMMA). R14.
// Shapes: UNITS=256, N=64, S=4, BATCH=64, T=1024.
// Grid: 256 blocks (1 unit) x 128 threads (4 warps). Warp w owns batches
// 16w..16w+15 (m16), full j range (n64). Per step: R = alpha @ A as 8 n-tiles
// x 4 k-chunks of m16n8k16. KEY: the D-accumulator fragment layout equals the
// A-operand fragment layout, so normalized+bf16-converted fw IS next step's
// A-fragment: alpha lives entirely in registers, zero shuffles/smem for the
// recurrence, and the time loop has NO __syncthreads.
// Transition matrix prepacked into exact B-fragment order (bf16x2 words) at
// setup; emission j-pairs and init j-pairs prepacked as f32x2.

#define NU 256
#define NN 64
#define NS 4
#define NB 64
#define NT 1024

typedef unsigned long long f2;
typedef unsigned u32;

__device__ __forceinline__ f2 pack2(float a, float b) {
    f2 r; asm("mov.b64 %0, {%1, %2};" : "=l"(r) : "f"(a), "f"(b)); return r;
}
__device__ __forceinline__ void unpack2(f2 v, float& a, float& b) {
    asm("mov.b64 {%0, %1}, %2;" : "=f"(a), "=f"(b) : "l"(v));
}
__device__ __forceinline__ f2 fma2(f2 a, f2 b, f2 c) {
    f2 d; asm("fma.rn.f32x2 %0, %1, %2, %3;" : "=l"(d) : "l"(a), "l"(b), "l"(c)); return d;
}
__device__ __forceinline__ f2 mul2(f2 a, f2 b) {
    f2 d; asm("mul.rn.f32x2 %0, %1, %2;" : "=l"(d) : "l"(a), "l"(b)); return d;
}
__device__ __forceinline__ f2 add2(f2 a, f2 b) {
    f2 d; asm("add.rn.f32x2 %0, %1, %2;" : "=l"(d) : "l"(a), "l"(b)); return d;
}
// bf16x2 word: {high half = hi, low half = lo}
__device__ __forceinline__ u32 cvtbf2(float hi, float lo) {
    u32 w; asm("cvt.rn.bf16x2.f32 %0, %1, %2;" : "=r"(w) : "f"(hi), "f"(lo)); return w;
}
__device__ __forceinline__ void mma16816(
    float& c0, float& c1, float& c2, float& c3,
    u32 a0, u32 a1, u32 a2, u32 a3, u32 b0, u32 b1)
{
    asm("mma.sync.aligned.m16n8k16.row.col.f32.bf16.bf16.f32 "
        "{%0,%1,%2,%3}, {%4,%5,%6,%7}, {%8,%9}, {%0,%1,%2,%3};"
        : "+f"(c0), "+f"(c1), "+f"(c2), "+f"(c3)
        : "r"(a0), "r"(a1), "r"(a2), "r"(a3), "r"(b0), "r"(b1));
}

__global__ void __launch_bounds__(128) hmm_fwd_kernel(
    const float* __restrict__ x,      // [B, T, S]
    const float* __restrict__ trans,  // [U, N, N]
    const float* __restrict__ emis,   // [U, N, S]
    const float* __restrict__ initk,  // [U, N]
    float* __restrict__ out)          // [B, T, U]
{
    __shared__ float Astage[NN * NN];         // softmaxed transition (f32)
    __shared__ u32   Bfrag[8 * 4 * 32 * 2];   // B-fragments [nt][kc][lane][2], 8KB
    __shared__ f2    Bem[8 * 4 * 4];          // emission j-pairs [nt][c][p]
    __shared__ f2    Ipair[32];               // init j-pairs [nt][p]
    __shared__ float Bsm[NN * NS];            // softmaxed emission (f32)
    __shared__ float I_sh[NN];
    __shared__ float Isum;

    const int tid  = threadIdx.x;
    const int u    = blockIdx.x;
    const int lane = tid & 31;
    const int warp = tid >> 5;
    const int r    = lane >> 2;   // 0..7
    const int p    = lane & 3;    // 0..3
    const int b_lo = warp * 16 + r;
    const int b_hi = b_lo + 8;

    // ---------------- setup ----------------
    const float* Tu = trans + u * NN * NN;
    for (int idx = tid; idx < NN * NN; idx += 128) Astage[idx] = Tu[idx];

    if (tid < NN) {
        const float* Eu = emis + (u * NN + tid) * NS;
        float e0 = expf(Eu[0]), e1 = expf(Eu[1]), e2 = expf(Eu[2]), e3 = expf(Eu[3]);
        float rr = 1.0f / ((e0 + e1) + (e2 + e3));
        Bsm[tid * 4 + 0] = e0 * rr; Bsm[tid * 4 + 1] = e1 * rr;
        Bsm[tid * 4 + 2] = e2 * rr; Bsm[tid * 4 + 3] = e3 * rr;
        I_sh[tid] = expf(initk[u * NN + tid]);
    }
    __syncthreads();

    if (tid < NN) {   // row softmax of transition row tid
        float s = 0.0f;
        #pragma unroll 8
        for (int j = 0; j < NN; ++j) {
            float e = expf(Astage[tid * NN + j]);
            Astage[tid * NN + j] = e;
            s += e;
        }
        float rr = 1.0f / s;
        #pragma unroll 8
        for (int j = 0; j < NN; ++j) Astage[tid * NN + j] *= rr;
    }
    if (tid == 0) {
        float s = 0.0f;
        #pragma unroll 8
        for (int k = 0; k < NN; ++k) s += I_sh[k];
        Isum = 1.0f / s;
    }
    __syncthreads();

    // B-fragment packing: Bop[k][n] = A[k][n] (col-major n8k16 frag).
    // word0 = {lo=A[k0][n], hi=A[k0+1][n]}, word1 = same with k0+8.
    for (int e = tid; e < 8 * 4 * 32; e += 128) {
        int nt = e >> 7, kc = (e >> 5) & 3, l = e & 31;
        int rr = l >> 2, pp = l & 3;
        int n  = nt * 8 + rr;
        int k0 = kc * 16 + 2 * pp;
        Bfrag[e * 2 + 0] = cvtbf2(Astage[(k0 + 1) * NN + n], Astage[k0 * NN + n]);
        Bfrag[e * 2 + 1] = cvtbf2(Astage[(k0 + 9) * NN + n], Astage[(k0 + 8) * NN + n]);
    }
    {   // Bem[(nt*4+c)*4+p] = {B[8nt+2p][c], B[8nt+2p+1][c]}
        int nt = tid >> 4, c = (tid >> 2) & 3, pp = tid & 3;
        Bem[tid] = pack2(Bsm[(8 * nt + 2 * pp) * NS + c],
                         Bsm[(8 * nt + 2 * pp + 1) * NS + c]);
    }
    if (tid < 32) {
        int nt = tid >> 2, pp = tid & 3;
        float inv = Isum;
        Ipair[tid] = pack2(I_sh[8 * nt + 2 * pp] * inv,
                           I_sh[8 * nt + 2 * pp + 1] * inv);
    }
    __syncthreads();

    // ---------------- time loop (no block syncs) ----------------
    const float4* x4 = (const float4*)x;
    float4 xlo = __ldg(&x4[b_lo * NT + 0]);
    float4 xhi = __ldg(&x4[b_hi * NT + 0]);

    u32 af[4][4];            // alpha A-fragments (bf16x2), set each step
    float ll_lo = 0.0f, ll_hi = 0.0f;

    for (int t = 0; t < NT; ++t) {
        // prefetch x_{t+1}
        int tn = (t + 1 < NT) ? (t + 1) : t;
        float4 xlo_n = __ldg(&x4[b_lo * NT + tn]);
        float4 xhi_n = __ldg(&x4[b_hi * NT + tn]);

        // x channel splats
        f2 xs0l = pack2(xlo.x, xlo.x), xs1l = pack2(xlo.y, xlo.y);
        f2 xs2l = pack2(xlo.z, xlo.z), xs3l = pack2(xlo.w, xlo.w);
        f2 xs0h = pack2(xhi.x, xhi.x), xs1h = pack2(xhi.y, xhi.y);
        f2 xs2h = pack2(xhi.z, xhi.z), xs3h = pack2(xhi.w, xhi.w);

        f2 fwlo[8], fwhi[8];

        if (t == 0) {
            #pragma unroll
            for (int nt = 0; nt < 8; ++nt) {
                f2 e_lo = mul2(Bem[(nt * 4 + 0) * 4 + p], xs0l);
                e_lo = fma2(Bem[(nt * 4 + 1) * 4 + p], xs1l, e_lo);
                e_lo = fma2(Bem[(nt * 4 + 2) * 4 + p], xs2l, e_lo);
                e_lo = fma2(Bem[(nt * 4 + 3) * 4 + p], xs3l, e_lo);
                f2 e_hi = mul2(Bem[(nt * 4 + 0) * 4 + p], xs0h);
                e_hi = fma2(Bem[(nt * 4 + 1) * 4 + p], xs1h, e_hi);
                e_hi = fma2(Bem[(nt * 4 + 2) * 4 + p], xs2h, e_hi);
                e_hi = fma2(Bem[(nt * 4 + 3) * 4 + p], xs3h, e_hi);
                f2 Ip = Ipair[nt * 4 + p];
                fwlo[nt] = mul2(e_lo, Ip);
                fwhi[nt] = mul2(e_hi, Ip);
            }
        } else {
            #pragma unroll
            for (int nt = 0; nt < 8; ++nt) {
                float c0 = 0.f, c1 = 0.f, c2 = 0.f, c3 = 0.f;
                #pragma unroll
                for (int kc = 0; kc < 4; ++kc) {
                    const u32* bp = &Bfrag[((nt * 4 + kc) * 32 + lane) * 2];
                    mma16816(c0, c1, c2, c3,
                             af[kc][0], af[kc][1], af[kc][2], af[kc][3],
                             bp[0], bp[1]);
                }
                f2 e_lo = mul2(Bem[(nt * 4 + 0) * 4 + p], xs0l);
                e_lo = fma2(Bem[(nt * 4 + 1) * 4 + p], xs1l, e_lo);
                e_lo = fma2(Bem[(nt * 4 + 2) * 4 + p], xs2l, e_lo);
                e_lo = fma2(Bem[(nt * 4 + 3) * 4 + p], xs3l, e_lo);
                f2 e_hi = mul2(Bem[(nt * 4 + 0) * 4 + p], xs0h);
                e_hi = fma2(Bem[(nt * 4 + 1) * 4 + p], xs1h, e_hi);
                e_hi = fma2(Bem[(nt * 4 + 2) * 4 + p], xs2h, e_hi);
                e_hi = fma2(Bem[(nt * 4 + 3) * 4 + p], xs3h, e_hi);
                fwlo[nt] = mul2(pack2(c0, c1), e_lo);
                fwhi[nt] = mul2(pack2(c2, c3), e_hi);
            }
        }

        // row sums over all 64 j: in-thread tree + quad butterfly
        f2 tl = add2(add2(add2(fwlo[0], fwlo[1]), add2(fwlo[2], fwlo[3])),
                     add2(add2(fwlo[4], fwlo[5]), add2(fwlo[6], fwlo[7])));
        f2 th = add2(add2(add2(fwhi[0], fwhi[1]), add2(fwhi[2], fwhi[3])),
                     add2(add2(fwhi[4], fwhi[5]), add2(fwhi[6], fwhi[7])));
        float sa, sb;
        unpack2(tl, sa, sb); float slo = sa + sb;
        unpack2(th, sa, sb); float shi = sa + sb;
        slo += __shfl_xor_sync(0xffffffffu, slo, 1);
        slo += __shfl_xor_sync(0xffffffffu, slo, 2);
        shi += __shfl_xor_sync(0xffffffffu, shi, 1);
        shi += __shfl_xor_sync(0xffffffffu, shi, 2);

        if (p == 0) {
            ll_lo += __logf(slo);
            ll_hi += __logf(shi);
            out[(b_lo * NT + t) * NU + u] = ll_lo;
            out[(b_hi * NT + t) * NU + u] = ll_hi;
        }

        // normalize + convert: D-fragment IS next step's A-fragment
        float rlo = __fdividef(1.0f, slo);
        float rhi = __fdividef(1.0f, shi);
        f2 r2lo = pack2(rlo, rlo), r2hi = pack2(rhi, rhi);
        #pragma unroll
        for (int kc = 0; kc < 4; ++kc) {
            float e0, o0;
            f2 v;
            v = mul2(fwlo[2 * kc], r2lo);     unpack2(v, e0, o0); af[kc][0] = cvtbf2(o0, e0);
            v = mul2(fwhi[2 * kc], r2hi);     unpack2(v, e0, o0); af[kc][1] = cvtbf2(o0, e0);
            v = mul2(fwlo[2 * kc + 1], r2lo); unpack2(v, e0, o0); af[kc][2] = cvtbf2(o0, e0);
            v = mul2(fwhi[2 * kc + 1], r2hi); unpack2(v, e0, o0); af[kc][3] = cvtbf2(o0, e0);
        }

        xlo = xlo_n;
        xhi = xhi_n;
    }
}

extern "C" void kernel_launch(void* const* d_in, const int* in_sizes, int n_in,
                              void* d_out, int out_size) {
    const float* x     = (const float*)d_in[0];  // [64,1024,4]
    const float* trans = (const float*)d_in[1];  // [256,64,64]
    const float* emis  = (const float*)d_in[2];  // [256,64,4]
    const float* initk = (const float*)d_in[3];  // [256,64]
    float* out = (float*)d_out;                  // [64,1024,256]
    (void)in_sizes; (void)n_in; (void)out_size;

    hmm_fwd_kernel<<<NU, 128>>>(x, trans, emis, initk, out);
}

// round 15
// speedup vs baseline: 39.6870x; 1.5860x over previous
#include <cuda_runtime.h>

// HMM forward via mma.sync m16n8k16 bf16. R15: all-register operands.
// Shapes: UNITS=256, N=64, S=4, BATCH=64, T=1024.
// Grid: 256 blocks (1 unit) x 128 threads (4 warps); warp w owns batches
// 16w..16w+15, full j range. Per step: E = x@B^T (8 MMAs, k zero-padded),
// R = alpha@A (32 MMAs), fw = E*R. Transition/emission fragments live in
// REGISTERS (time-invariant); alpha recurrence stays in registers via the
// D-frag == A-frag layout identity. 1/S normalization is folded into the
// next step's x (per-row scalar commutes through the j-matvec), so alpha
// converts to bf16 raw. Zero shared-memory traffic in the time loop.

#define NU 256
#define NN 64
#define NS 4
#define NB 64
#define NT 1024

typedef unsigned long long f2;
typedef unsigned u32;

__device__ __forceinline__ f2 pack2(float a, float b) {
    f2 r; asm("mov.b64 %0, {%1, %2};" : "=l"(r) : "f"(a), "f"(b)); return r;
}
__device__ __forceinline__ void unpack2(f2 v, float& a, float& b) {
    asm("mov.b64 {%0, %1}, %2;" : "=f"(a), "=f"(b) : "l"(v));
}
__device__ __forceinline__ f2 mul2(f2 a, f2 b) {
    f2 d; asm("mul.rn.f32x2 %0, %1, %2;" : "=l"(d) : "l"(a), "l"(b)); return d;
}
__device__ __forceinline__ f2 add2(f2 a, f2 b) {
    f2 d; asm("add.rn.f32x2 %0, %1, %2;" : "=l"(d) : "l"(a), "l"(b)); return d;
}
// bf16x2 word: {high half = bf(hi), low half = bf(lo)}
__device__ __forceinline__ u32 cvtbf2(float hi, float lo) {
    u32 w; asm("cvt.rn.bf16x2.f32 %0, %1, %2;" : "=r"(w) : "f"(hi), "f"(lo)); return w;
}
__device__ __forceinline__ void mma16816(
    float& c0, float& c1, float& c2, float& c3,
    u32 a0, u32 a1, u32 a2, u32 a3, u32 b0, u32 b1)
{
    asm("mma.sync.aligned.m16n8k16.row.col.f32.bf16.bf16.f32 "
        "{%0,%1,%2,%3}, {%4,%5,%6,%7}, {%8,%9}, {%0,%1,%2,%3};"
        : "+f"(c0), "+f"(c1), "+f"(c2), "+f"(c3)
        : "r"(a0), "r"(a1), "r"(a2), "r"(a3), "r"(b0), "r"(b1));
}

__global__ void __launch_bounds__(128) hmm_fwd_kernel(
    const float* __restrict__ x,      // [B, T, S]
    const float* __restrict__ trans,  // [U, N, N]
    const float* __restrict__ emis,   // [U, N, S]
    const float* __restrict__ initk,  // [U, N]
    float* __restrict__ out)          // [B, T, U]
{
    __shared__ float Astage[NN * NN];   // softmaxed transition (f32), setup only
    __shared__ float Bsm[NN * NS];      // softmaxed emission (f32), setup only
    __shared__ f2    Ipair[32];         // init j-pairs [nt][p]
    __shared__ float I_sh[NN];
    __shared__ float Isum;

    const int tid  = threadIdx.x;
    const int u    = blockIdx.x;
    const int lane = tid & 31;
    const int warp = tid >> 5;
    const int r    = lane >> 2;   // 0..7
    const int p    = lane & 3;    // 0..3
    const int b_lo = warp * 16 + r;
    const int b_hi = b_lo + 8;

    // ---------------- setup ----------------
    const float* Tu = trans + u * NN * NN;
    for (int idx = tid; idx < NN * NN; idx += 128) Astage[idx] = Tu[idx];

    if (tid < NN) {
        const float* Eu = emis + (u * NN + tid) * NS;
        float e0 = expf(Eu[0]), e1 = expf(Eu[1]), e2 = expf(Eu[2]), e3 = expf(Eu[3]);
        float rr = 1.0f / ((e0 + e1) + (e2 + e3));
        Bsm[tid * 4 + 0] = e0 * rr; Bsm[tid * 4 + 1] = e1 * rr;
        Bsm[tid * 4 + 2] = e2 * rr; Bsm[tid * 4 + 3] = e3 * rr;
        I_sh[tid] = expf(initk[u * NN + tid]);
    }
    __syncthreads();

    if (tid < NN) {   // row softmax of transition row tid
        float s = 0.0f;
        #pragma unroll 8
        for (int j = 0; j < NN; ++j) {
            float e = expf(Astage[tid * NN + j]);
            Astage[tid * NN + j] = e;
            s += e;
        }
        float rr = 1.0f / s;
        #pragma unroll 8
        for (int j = 0; j < NN; ++j) Astage[tid * NN + j] *= rr;
    }
    if (tid == 0) {
        float s = 0.0f;
        #pragma unroll 8
        for (int k = 0; k < NN; ++k) s += I_sh[k];
        Isum = 1.0f / s;
    }
    __syncthreads();

    if (tid < 32) {
        int nt = tid >> 2, pp = tid & 3;
        float inv = Isum;
        Ipair[tid] = pack2(I_sh[8 * nt + 2 * pp] * inv,
                           I_sh[8 * nt + 2 * pp + 1] * inv);
    }

    // Transition B-fragments in REGISTERS: per (nt, kc):
    // word0 = {lo=A[k0][n], hi=A[k0+1][n]}, word1 = {A[k0+8][n], A[k0+9][n]}
    // with n = 8*nt + r, k0 = 16*kc + 2*p.
    u32 bA[8][4][2];
    #pragma unroll
    for (int nt = 0; nt < 8; ++nt) {
        const int n = nt * 8 + r;
        #pragma unroll
        for (int kc = 0; kc < 4; ++kc) {
            const int k0 = kc * 16 + 2 * p;
            bA[nt][kc][0] = cvtbf2(Astage[(k0 + 1) * NN + n], Astage[k0 * NN + n]);
            bA[nt][kc][1] = cvtbf2(Astage[(k0 + 9) * NN + n], Astage[(k0 + 8) * NN + n]);
        }
    }
    // Emission B-fragments (E-MMA, k = channel, only k<4 valid -> p<2 lanes):
    u32 bE[8];
    #pragma unroll
    for (int nt = 0; nt < 8; ++nt) {
        const int j = 8 * nt + r;
        bE[nt] = (p < 2) ? cvtbf2(Bsm[j * 4 + 2 * p + 1], Bsm[j * 4 + 2 * p]) : 0u;
    }
    __syncthreads();

    // ---------------- time loop (no block syncs, no smem traffic) ----------
    const float* xb_lo = x + (size_t)b_lo * NT * 4 + (p & 1) * 2;
    const float* xb_hi = x + (size_t)b_hi * NT * 4 + (p & 1) * 2;
    float2 xl = __ldg((const float2*)xb_lo);
    float2 xh = __ldg((const float2*)xb_hi);

    u32 af[4][4];                         // alpha A-fragments (bf16x2)
    float rlo_p = 1.0f, rhi_p = 1.0f;     // 1/S from previous step
    float ll_lo = 0.0f, ll_hi = 0.0f;

    for (int t = 0; t < NT; ++t) {
        // x A-fragment words, scaled by previous 1/S (normalization folding)
        u32 xa0, xa1;
        {
            float a, b;
            f2 v = mul2(pack2(xl.x, xl.y), pack2(rlo_p, rlo_p));
            unpack2(v, a, b); xa0 = cvtbf2(b, a);
            v = mul2(pack2(xh.x, xh.y), pack2(rhi_p, rhi_p));
            unpack2(v, a, b); xa1 = cvtbf2(b, a);
            if (p >= 2) { xa0 = 0u; xa1 = 0u; }
        }
        // prefetch x_{t+1}
        int tn = (t + 1 < NT) ? (t + 1) : t;
        float2 xl_n = __ldg((const float2*)(xb_lo + (size_t)tn * 4));
        float2 xh_n = __ldg((const float2*)(xb_hi + (size_t)tn * 4));

        // E = x @ B^T  (8 MMAs, k zero-padded)
        float ef[8][4];
        #pragma unroll
        for (int nt = 0; nt < 8; ++nt) {
            ef[nt][0] = 0.f; ef[nt][1] = 0.f; ef[nt][2] = 0.f; ef[nt][3] = 0.f;
            mma16816(ef[nt][0], ef[nt][1], ef[nt][2], ef[nt][3],
                     xa0, xa1, 0u, 0u, bE[nt], 0u);
        }

        f2 fwlo[8], fwhi[8];
        if (t == 0) {
            #pragma unroll
            for (int nt = 0; nt < 8; ++nt) {
                f2 Ip = Ipair[nt * 4 + p];
                fwlo[nt] = mul2(pack2(ef[nt][0], ef[nt][1]), Ip);
                fwhi[nt] = mul2(pack2(ef[nt][2], ef[nt][3]), Ip);
            }
        } else {
            #pragma unroll
            for (int nt = 0; nt < 8; ++nt) {
                float c0 = 0.f, c1 = 0.f, c2 = 0.f, c3 = 0.f;
                #pragma unroll
                for (int kc = 0; kc < 4; ++kc)
                    mma16816(c0, c1, c2, c3,
                             af[kc][0], af[kc][1], af[kc][2], af[kc][3],
                             bA[nt][kc][0], bA[nt][kc][1]);
                fwlo[nt] = mul2(pack2(c0, c1), pack2(ef[nt][0], ef[nt][1]));
                fwhi[nt] = mul2(pack2(c2, c3), pack2(ef[nt][2], ef[nt][3]));
            }
        }

        // row sums over all 64 j: in-thread tree + quad butterfly
        f2 tl = add2(add2(add2(fwlo[0], fwlo[1]), add2(fwlo[2], fwlo[3])),
                     add2(add2(fwlo[4], fwlo[5]), add2(fwlo[6], fwlo[7])));
        f2 th = add2(add2(add2(fwhi[0], fwhi[1]), add2(fwhi[2], fwhi[3])),
                     add2(add2(fwhi[4], fwhi[5]), add2(fwhi[6], fwhi[7])));
        float sa, sb;
        unpack2(tl, sa, sb); float slo = sa + sb;
        unpack2(th, sa, sb); float shi = sa + sb;
        slo += __shfl_xor_sync(0xffffffffu, slo, 1);
        slo += __shfl_xor_sync(0xffffffffu, slo, 2);
        shi += __shfl_xor_sync(0xffffffffu, shi, 1);
        shi += __shfl_xor_sync(0xffffffffu, shi, 2);

        if (p == 0) {
            ll_lo += __logf(slo);
            ll_hi += __logf(shi);
            out[((size_t)b_lo * NT + t) * NU + u] = ll_lo;
            out[((size_t)b_hi * NT + t) * NU + u] = ll_hi;
        }

        // next-step 1/S (applied to x at the top of the next iteration)
        rlo_p = __fdividef(1.0f, slo);
        rhi_p = __fdividef(1.0f, shi);

        // af = bf16(raw fw): D-fragment IS next step's A-fragment
        #pragma unroll
        for (int kc = 0; kc < 4; ++kc) {
            float e0, o0;
            unpack2(fwlo[2 * kc],     e0, o0); af[kc][0] = cvtbf2(o0, e0);
            unpack2(fwhi[2 * kc],     e0, o0); af[kc][1] = cvtbf2(o0, e0);
            unpack2(fwlo[2 * kc + 1], e0, o0); af[kc][2] = cvtbf2(o0, e0);
            unpack2(fwhi[2 * kc + 1], e0, o0); af[kc][3] = cvtbf2(o0, e0);
        }

        xl = xl_n;
        xh = xh_n;
    }
}

extern "C" void kernel_launch(void* const* d_in, const int* in_sizes, int n_in,
                              void* d_out, int out_size) {
    const float* x     = (const float*)d_in[0];  // [64,1024,4]
    const float* trans = (const float*)d_in[1];  // [256,64,64]
    const float* emis  = (const float*)d_in[2];  // [256,64,4]
    const float* initk = (const float*)d_in[3];  // [256,64]
    float* out = (float*)d_out;                  // [64,1024,256]
    (void)in_sizes; (void)n_in; (void)out_size;

    hmm_fwd_kernel<<<NU, 128>>>(x, trans, emis, initk, out);
}

// round 16
// speedup vs baseline: 42.9072x; 1.0811x over previous
#include <cuda_runtime.h>

// HMM forward via mma.sync m16n8k16 bf16. R16: lazy renormalization.
// Shapes: UNITS=256, N=64, S=4, BATCH=64, T=1024.
// Grid: 256 blocks (1 unit) x 128 threads (4 warps); warp w owns batches
// 16w..16w+15, full j range. Recurrence runs UNNORMALIZED (it is linear);
// ll(t) = C + log(sum(fw_t)), C accumulating logs of lazy rescales.
// Every 8 steps fw is rescaled by 1/g_{t-1} (one step STALE, so the divide
// is off the critical path) and C += log(g_{t-1}) BEFORE the output, keeping
// ll exact. Critical path: fw -> cvt -> 2-serial MMA -> fw. All operands in
// registers; zero smem traffic and zero block syncs in the time loop.

#define NU 256
#define NN 64
#define NS 4
#define NB 64
#define NT 1024

typedef unsigned long long f2;
typedef unsigned u32;

__device__ __forceinline__ f2 pack2(float a, float b) {
    f2 r; asm("mov.b64 %0, {%1, %2};" : "=l"(r) : "f"(a), "f"(b)); return r;
}
__device__ __forceinline__ void unpack2(f2 v, float& a, float& b) {
    asm("mov.b64 {%0, %1}, %2;" : "=f"(a), "=f"(b) : "l"(v));
}
__device__ __forceinline__ f2 mul2(f2 a, f2 b) {
    f2 d; asm("mul.rn.f32x2 %0, %1, %2;" : "=l"(d) : "l"(a), "l"(b)); return d;
}
__device__ __forceinline__ f2 add2(f2 a, f2 b) {
    f2 d; asm("add.rn.f32x2 %0, %1, %2;" : "=l"(d) : "l"(a), "l"(b)); return d;
}
__device__ __forceinline__ u32 cvtbf2(float hi, float lo) {
    u32 w; asm("cvt.rn.bf16x2.f32 %0, %1, %2;" : "=r"(w) : "f"(hi), "f"(lo)); return w;
}
__device__ __forceinline__ void mma16816(
    float& c0, float& c1, float& c2, float& c3,
    u32 a0, u32 a1, u32 a2, u32 a3, u32 b0, u32 b1)
{
    asm("mma.sync.aligned.m16n8k16.row.col.f32.bf16.bf16.f32 "
        "{%0,%1,%2,%3}, {%4,%5,%6,%7}, {%8,%9}, {%0,%1,%2,%3};"
        : "+f"(c0), "+f"(c1), "+f"(c2), "+f"(c3)
        : "r"(a0), "r"(a1), "r"(a2), "r"(a3), "r"(b0), "r"(b1));
}

__global__ void __launch_bounds__(128) hmm_fwd_kernel(
    const float* __restrict__ x,      // [B, T, S]
    const float* __restrict__ trans,  // [U, N, N]
    const float* __restrict__ emis,   // [U, N, S]
    const float* __restrict__ initk,  // [U, N]
    float* __restrict__ out)          // [B, T, U]
{
    __shared__ float Astage[NN * NN];
    __shared__ float Bsm[NN * NS];
    __shared__ f2    Ipair[32];
    __shared__ float I_sh[NN];
    __shared__ float Isum;

    const int tid  = threadIdx.x;
    const int u    = blockIdx.x;
    const int lane = tid & 31;
    const int warp = tid >> 5;
    const int r    = lane >> 2;
    const int p    = lane & 3;
    const int b_lo = warp * 16 + r;
    const int b_hi = b_lo + 8;

    // ---------------- setup ----------------
    const float* Tu = trans + u * NN * NN;
    for (int idx = tid; idx < NN * NN; idx += 128) Astage[idx] = Tu[idx];

    if (tid < NN) {
        const float* Eu = emis + (u * NN + tid) * NS;
        float e0 = expf(Eu[0]), e1 = expf(Eu[1]), e2 = expf(Eu[2]), e3 = expf(Eu[3]);
        float rr = 1.0f / ((e0 + e1) + (e2 + e3));
        Bsm[tid * 4 + 0] = e0 * rr; Bsm[tid * 4 + 1] = e1 * rr;
        Bsm[tid * 4 + 2] = e2 * rr; Bsm[tid * 4 + 3] = e3 * rr;
        I_sh[tid] = expf(initk[u * NN + tid]);
    }
    __syncthreads();

    if (tid < NN) {
        float s = 0.0f;
        #pragma unroll 8
        for (int j = 0; j < NN; ++j) {
            float e = expf(Astage[tid * NN + j]);
            Astage[tid * NN + j] = e;
            s += e;
        }
        float rr = 1.0f / s;
        #pragma unroll 8
        for (int j = 0; j < NN; ++j) Astage[tid * NN + j] *= rr;
    }
    if (tid == 0) {
        float s = 0.0f;
        #pragma unroll 8
        for (int k = 0; k < NN; ++k) s += I_sh[k];
        Isum = 1.0f / s;
    }
    __syncthreads();

    if (tid < 32) {
        int nt = tid >> 2, pp = tid & 3;
        float inv = Isum;
        Ipair[tid] = pack2(I_sh[8 * nt + 2 * pp] * inv,
                           I_sh[8 * nt + 2 * pp + 1] * inv);
    }

    u32 bA[8][4][2];
    #pragma unroll
    for (int nt = 0; nt < 8; ++nt) {
        const int n = nt * 8 + r;
        #pragma unroll
        for (int kc = 0; kc < 4; ++kc) {
            const int k0 = kc * 16 + 2 * p;
            bA[nt][kc][0] = cvtbf2(Astage[(k0 + 1) * NN + n], Astage[k0 * NN + n]);
            bA[nt][kc][1] = cvtbf2(Astage[(k0 + 9) * NN + n], Astage[(k0 + 8) * NN + n]);
        }
    }
    u32 bE[8];
    #pragma unroll
    for (int nt = 0; nt < 8; ++nt) {
        const int j = 8 * nt + r;
        bE[nt] = (p < 2) ? cvtbf2(Bsm[j * 4 + 2 * p + 1], Bsm[j * 4 + 2 * p]) : 0u;
    }
    __syncthreads();

    // ---------------- time loop ----------------
    const float* xb_lo = x + (size_t)b_lo * NT * 4 + (p & 1) * 2;
    const float* xb_hi = x + (size_t)b_hi * NT * 4 + (p & 1) * 2;
    float2 xl = __ldg((const float2*)xb_lo);
    float2 xh = __ldg((const float2*)xb_hi);

    u32 af[4][4];
    float g_lo_p = 1.0f, g_hi_p = 1.0f;     // g from previous step
    float lg_lo_p = 0.0f, lg_hi_p = 0.0f;   // log of same
    float C_lo = 0.0f, C_hi = 0.0f;

    for (int t = 0; t < NT; ++t) {
        const bool do_rn = ((t & 7) == 7);
        float ml = 1.0f, mh = 1.0f;
        if (do_rn) {
            ml = __fdividef(1.0f, g_lo_p);
            mh = __fdividef(1.0f, g_hi_p);
            C_lo += lg_lo_p;          // BEFORE output: ll(t) = C + log(g*ml)
            C_hi += lg_hi_p;          //   = (C+log g_{t-1}) + log g_t - log g_{t-1}
        }

        u32 xa0 = cvtbf2(xl.y, xl.x);
        u32 xa1 = cvtbf2(xh.y, xh.x);
        if (p >= 2) { xa0 = 0u; xa1 = 0u; }

        int tn = (t + 1 < NT) ? (t + 1) : t;
        float2 xl_n = __ldg((const float2*)(xb_lo + (size_t)tn * 4));
        float2 xh_n = __ldg((const float2*)(xb_hi + (size_t)tn * 4));

        // E = x @ B^T (8 MMAs, k zero-padded)
        float ef[8][4];
        #pragma unroll
        for (int nt = 0; nt < 8; ++nt) {
            ef[nt][0] = 0.f; ef[nt][1] = 0.f; ef[nt][2] = 0.f; ef[nt][3] = 0.f;
            mma16816(ef[nt][0], ef[nt][1], ef[nt][2], ef[nt][3],
                     xa0, xa1, 0u, 0u, bE[nt], 0u);
        }

        f2 fwlo[8], fwhi[8];
        if (t == 0) {
            #pragma unroll
            for (int nt = 0; nt < 8; ++nt) {
                f2 Ip = Ipair[nt * 4 + p];
                fwlo[nt] = mul2(pack2(ef[nt][0], ef[nt][1]), Ip);
                fwhi[nt] = mul2(pack2(ef[nt][2], ef[nt][3]), Ip);
            }
        } else {
            #pragma unroll
            for (int nt = 0; nt < 8; ++nt) {
                // split accumulators: 2-deep serial HMMA chains
                float a0 = 0.f, a1 = 0.f, a2 = 0.f, a3 = 0.f;
                float d0 = 0.f, d1 = 0.f, d2 = 0.f, d3 = 0.f;
                mma16816(a0, a1, a2, a3, af[0][0], af[0][1], af[0][2], af[0][3],
                         bA[nt][0][0], bA[nt][0][1]);
                mma16816(d0, d1, d2, d3, af[1][0], af[1][1], af[1][2], af[1][3],
                         bA[nt][1][0], bA[nt][1][1]);
                mma16816(a0, a1, a2, a3, af[2][0], af[2][1], af[2][2], af[2][3],
                         bA[nt][2][0], bA[nt][2][1]);
                mma16816(d0, d1, d2, d3, af[3][0], af[3][1], af[3][2], af[3][3],
                         bA[nt][3][0], bA[nt][3][1]);
                f2 rlo = add2(pack2(a0, a1), pack2(d0, d1));
                f2 rhi = add2(pack2(a2, a3), pack2(d2, d3));
                fwlo[nt] = mul2(rlo, pack2(ef[nt][0], ef[nt][1]));
                fwhi[nt] = mul2(rhi, pack2(ef[nt][2], ef[nt][3]));
            }
        }

        // rescale (rare, uniform branch) — fw now carries the multiplier, so
        // both af and this step's g are consistently scaled.
        if (do_rn) {
            f2 m2l = pack2(ml, ml), m2h = pack2(mh, mh);
            #pragma unroll
            for (int nt = 0; nt < 8; ++nt) {
                fwlo[nt] = mul2(fwlo[nt], m2l);
                fwhi[nt] = mul2(fwhi[nt], m2h);
            }
        }

        // CRITICAL PATH: af = bf16(fw) feeds next step's MMAs
        #pragma unroll
        for (int kc = 0; kc < 4; ++kc) {
            float e0, o0;
            unpack2(fwlo[2 * kc],     e0, o0); af[kc][0] = cvtbf2(o0, e0);
            unpack2(fwhi[2 * kc],     e0, o0); af[kc][1] = cvtbf2(o0, e0);
            unpack2(fwlo[2 * kc + 1], e0, o0); af[kc][2] = cvtbf2(o0, e0);
            unpack2(fwhi[2 * kc + 1], e0, o0); af[kc][3] = cvtbf2(o0, e0);
        }

        // SIDE: g = row sums; feeds output + next rescale only
        f2 tl = add2(add2(add2(fwlo[0], fwlo[1]), add2(fwlo[2], fwlo[3])),
                     add2(add2(fwlo[4], fwlo[5]), add2(fwlo[6], fwlo[7])));
        f2 th = add2(add2(add2(fwhi[0], fwhi[1]), add2(fwhi[2], fwhi[3])),
                     add2(add2(fwhi[4], fwhi[5]), add2(fwhi[6], fwhi[7])));
        float sa, sb;
        unpack2(tl, sa, sb); float slo = sa + sb;
        unpack2(th, sa, sb); float shi = sa + sb;
        slo += __shfl_xor_sync(0xffffffffu, slo, 1);
        slo += __shfl_xor_sync(0xffffffffu, slo, 2);
        shi += __shfl_xor_sync(0xffffffffu, shi, 1);
        shi += __shfl_xor_sync(0xffffffffu, shi, 2);

        float lg_lo = __logf(slo);
        float lg_hi = __logf(shi);
        if (p == 0) {
            out[((size_t)b_lo * NT + t) * NU + u] = C_lo + lg_lo;
            out[((size_t)b_hi * NT + t) * NU + u] = C_hi + lg_hi;
        }

        g_lo_p = slo;  g_hi_p = shi;
        lg_lo_p = lg_lo; lg_hi_p = lg_hi;
        xl = xl_n;
        xh = xh_n;
    }
}

extern "C" void kernel_launch(void* const* d_in, const int* in_sizes, int n_in,
                              void* d_out, int out_size) {
    const float* x     = (const float*)d_in[0];  // [64,1024,4]
    const float* trans = (const float*)d_in[1];  // [256,64,64]
    const float* emis  = (const float*)d_in[2];  // [256,64,4]
    const float* initk = (const float*)d_in[3];  // [256,64]
    float* out = (float*)d_out;                  // [64,1024,256]
    (void)in_sizes; (void)n_in; (void)out_size;

    hmm_fwd_kernel<<<NU, 128>>>(x, trans, emis, initk, out);
}